// round 13
// baseline (speedup 1.0000x reference)
#include <cuda_runtime.h>
#include <cuda_fp16.h>
#include <math.h>

// ---------------- problem constants ----------------
#define Bb   4
#define Tt   8000
#define DIMN 512
#define Hh   8
#define DHd  64
#define Cc   200
#define NBb  40
#define Mm   (Bb*Tt)        // 32000
#define NJ   (Bb*NBb*Hh)    // 1280
#define SCALE 0.125f
#define LOG2E 1.4426950408889634f

// ---------------- scratch (device globals; no allocation allowed) ----------------
__device__ __half g_xn [Mm*DIMN];
__device__ __half g_q  [Mm*DIMN];
__device__ __half g_kv [Mm*2*DIMN];
__device__ __half g_rel[Cc*Cc*DHd];
__device__ __half g_pos[(size_t)NJ*Cc*Cc];   // [j][c][r], scaled
__device__ __half g_att[Mm*DIMN];
__device__ __half g_wqT [DIMN*DIMN];         // [N][K]
__device__ __half g_wkvT[2*DIMN*DIMN];       // [N][K]
__device__ __half g_woT [DIMN*DIMN];         // [N][K]

__device__ __forceinline__ float exp2poly(float y) {
    y = fmaxf(y, -126.f);
    float tt = y + 12582912.f;
    float r  = y - (tt - 12582912.f);
    int   ni = __float_as_int(tt) - 0x4B400000;
    float p = 1.33336e-3f;
    p = fmaf(p, r, 9.61812e-3f);
    p = fmaf(p, r, 5.55041e-2f);
    p = fmaf(p, r, 2.402265e-1f);
    p = fmaf(p, r, 6.931472e-1f);
    p = fmaf(p, r, 1.f);
    return p * __int_as_float((ni + 127) << 23);
}

__device__ __forceinline__ unsigned h2u(float a, float b) {
    __half2 h = __floats2half2_rn(a, b);
    return *(unsigned*)&h;
}

// ---------------- weight transpose+convert: dst[n][k] = (half)src[k][n] ----------------
__global__ void transpose_h(const float* __restrict__ src, __half* __restrict__ dst,
                            int K, int N) {
    __shared__ float tile[32][33];
    int k0 = blockIdx.x*32, n0 = blockIdx.y*32;
    int tx = threadIdx.x & 31, ty = threadIdx.x >> 5;
    #pragma unroll
    for (int i = 0; i < 4; i++)
        tile[ty*4+i][tx] = src[(size_t)(k0+ty*4+i)*N + n0 + tx];
    __syncthreads();
    #pragma unroll
    for (int i = 0; i < 4; i++)
        dst[(size_t)(n0+ty*4+i)*K + k0 + tx] = __float2half(tile[tx][ty*4+i]);
}

// ---------------- LayerNorm ----------------
__global__ void ln_kernel(const float* __restrict__ x,
                          const float* __restrict__ g,
                          const float* __restrict__ bta) {
    int row = blockIdx.x;
    int t = threadIdx.x;
    float4 v = ((const float4*)(x + (size_t)row*DIMN))[t];
    float s  = v.x + v.y + v.z + v.w;
    float ss = v.x*v.x + v.y*v.y + v.z*v.z + v.w*v.w;
    #pragma unroll
    for (int o = 16; o; o >>= 1) {
        s  += __shfl_xor_sync(~0u, s,  o);
        ss += __shfl_xor_sync(~0u, ss, o);
    }
    __shared__ float rs[4], rss[4];
    int w = t >> 5;
    if ((t & 31) == 0) { rs[w] = s; rss[w] = ss; }
    __syncthreads();
    s  = rs[0]  + rs[1]  + rs[2]  + rs[3];
    ss = rss[0] + rss[1] + rss[2] + rss[3];
    float mu  = s  * (1.0f/DIMN);
    float var = ss * (1.0f/DIMN) - mu*mu;
    float inv = rsqrtf(var + 1e-5f);
    float4 gg = ((const float4*)g)[t];
    float4 bb = ((const float4*)bta)[t];
    uint2 o;
    o.x = h2u((v.x-mu)*inv*gg.x + bb.x, (v.y-mu)*inv*gg.y + bb.y);
    o.y = h2u((v.z-mu)*inv*gg.z + bb.z, (v.w-mu)*inv*gg.w + bb.w);
    ((uint2*)(g_xn + (size_t)row*DIMN))[t] = o;
}

// ---------------- rel gather (half) ----------------
__global__ void gather_kernel(const int* __restrict__ dists,
                              const float* __restrict__ pe) {
    int idx = blockIdx.x*256 + threadIdx.x;
    if (idx < Cc*Cc*DHd) {
        int cr = idx >> 6, d = idx & 63;
        g_rel[idx] = __float2half(pe[dists[cr]*DHd + d]);
    }
}

// ---------------- fp16 mma helper ----------------
__device__ __forceinline__ void mma16(float* c, const unsigned* a, const unsigned* b) {
    asm volatile("mma.sync.aligned.m16n8k16.row.col.f32.f16.f16.f32 "
        "{%0,%1,%2,%3}, {%4,%5,%6,%7}, {%8,%9}, {%0,%1,%2,%3};"
        : "+f"(c[0]), "+f"(c[1]), "+f"(c[2]), "+f"(c[3])
        : "r"(a[0]), "r"(a[1]), "r"(a[2]), "r"(a[3]), "r"(b[0]), "r"(b[1]));
}

// ---------------- fp16 GEMM: BK=16, 4-stage cp.async (round-8 proven) ----------------
#define BM 128
#define BN 128
#define HST 24
#define H_ST (128*HST)                    // halves per stage (A or B)
#define G_SMEM (4*2*H_ST*2)               // 49,152 B

__device__ __forceinline__ void g_copy_h(
    const __half* __restrict__ A, const __half* __restrict__ WT,
    __half* As_st, __half* Bs_st, int m0, int n0, int k0, int tid)
{
    int row = tid >> 1, ch = tid & 1;
    unsigned da = (unsigned)__cvta_generic_to_shared(As_st + row*HST + ch*8);
    const __half* ga = A + (size_t)(m0 + row)*DIMN + k0 + ch*8;
    asm volatile("cp.async.cg.shared.global [%0], [%1], 16;" :: "r"(da), "l"(ga));
    unsigned db = (unsigned)__cvta_generic_to_shared(Bs_st + row*HST + ch*8);
    const __half* gb = WT + (size_t)(n0 + row)*DIMN + k0 + ch*8;
    asm volatile("cp.async.cg.shared.global [%0], [%1], 16;" :: "r"(db), "l"(gb));
}

template<bool HOUT>
__global__ __launch_bounds__(256, 2)
void gemm_h(const __half* __restrict__ A, const __half* __restrict__ WT,
            const float* __restrict__ bias, void* __restrict__ outp, int N) {
    extern __shared__ __half hsm[];
    int tid  = threadIdx.x;
    int lane = tid & 31, warp = tid >> 5;
    int wm = warp >> 2, wn = warp & 3;
    int g = lane >> 2, t = lane & 3;
    int m0 = blockIdx.y*BM, n0 = blockIdx.x*BN;

    float acc[4][4][4];
    #pragma unroll
    for (int i=0;i<4;i++)
        #pragma unroll
        for (int jx=0;jx<4;jx++)
            #pragma unroll
            for (int r=0;r<4;r++) acc[i][jx][r]=0.f;

    const int NIT = DIMN / 16;   // 32
    #pragma unroll
    for (int s = 0; s < 3; s++) {
        g_copy_h(A, WT, hsm + s*2*H_ST, hsm + s*2*H_ST + H_ST, m0, n0, s*16, tid);
        asm volatile("cp.async.commit_group;");
    }

    for (int it = 0; it < NIT; it++) {
        asm volatile("cp.async.wait_group 2;");
        __syncthreads();
        int buf = it & 3;
        const __half* Apt = hsm + buf*2*H_ST;
        const __half* Bpt = Apt + H_ST;
        unsigned af[4][4], bf[4][2];
        #pragma unroll
        for (int mt = 0; mt < 4; mt++) {
            int mb = wm*64 + mt*16 + g;
            af[mt][0] = *(const unsigned*)&Apt[ mb   *HST + 2*t];
            af[mt][1] = *(const unsigned*)&Apt[(mb+8)*HST + 2*t];
            af[mt][2] = *(const unsigned*)&Apt[ mb   *HST + 2*t + 8];
            af[mt][3] = *(const unsigned*)&Apt[(mb+8)*HST + 2*t + 8];
        }
        #pragma unroll
        for (int nt = 0; nt < 4; nt++) {
            int nb = wn*32 + nt*8 + g;
            bf[nt][0] = *(const unsigned*)&Bpt[nb*HST + 2*t];
            bf[nt][1] = *(const unsigned*)&Bpt[nb*HST + 2*t + 8];
        }
        #pragma unroll
        for (int mt = 0; mt < 4; mt++)
            #pragma unroll
            for (int nt = 0; nt < 4; nt++)
                mma16(acc[mt][nt], af[mt], bf[nt]);
        int nxt = it + 3;
        if (nxt < NIT) {
            int sb = nxt & 3;
            g_copy_h(A, WT, hsm + sb*2*H_ST, hsm + sb*2*H_ST + H_ST, m0, n0, nxt*16, tid);
        }
        asm volatile("cp.async.commit_group;");
    }

    #pragma unroll
    for (int mt = 0; mt < 4; mt++) {
        int row = m0 + wm*64 + mt*16 + g;
        #pragma unroll
        for (int nt = 0; nt < 4; nt++) {
            int col = n0 + wn*32 + nt*8 + 2*t;
            if (HOUT) {
                __half* out = (__half*)outp;
                *(unsigned*)(out + (size_t)row*N + col)     = h2u(acc[mt][nt][0], acc[mt][nt][1]);
                *(unsigned*)(out + (size_t)(row+8)*N + col) = h2u(acc[mt][nt][2], acc[mt][nt][3]);
            } else {
                float* out = (float*)outp;
                float bv0 = bias ? bias[col]   : 0.f;
                float bv1 = bias ? bias[col+1] : 0.f;
                *(float2*)(out + (size_t)row*N + col) =
                    make_float2(acc[mt][nt][0]+bv0, acc[mt][nt][1]+bv1);
                *(float2*)(out + (size_t)(row+8)*N + col) =
                    make_float2(acc[mt][nt][2]+bv0, acc[mt][nt][3]+bv1);
            }
        }
    }
}

// ---------------- pos bias via fp16 MMA (round-8 version) ----------------
#define PST 72
#define PM_SMEM ((64*PST + 208*PST)*2)
__global__ __launch_bounds__(256)
void pos_mma() {
    extern __shared__ __half psm[];
    __half* Qs = psm;
    __half* Rs = psm + 64*PST;
    int tid = threadIdx.x, lane = tid & 31, warp = tid >> 5;
    int wm = warp >> 1, wn = warp & 1;
    int g = lane >> 2, t = lane & 3;
    int c  = blockIdx.y;
    int j0 = blockIdx.x * 64;

    for (int i4 = tid; i4 < 208*8; i4 += 256) {
        int r = i4 >> 3, ch = (i4 & 7) * 8;
        uint4 v = make_uint4(0,0,0,0);
        if (r < Cc) v = *(const uint4*)(g_rel + ((size_t)c*Cc + r)*DHd + ch);
        *(uint4*)&Rs[r*PST + ch] = v;
    }
    for (int i4 = tid; i4 < 64*8; i4 += 256) {
        int jj = i4 >> 3, ch = (i4 & 7) * 8;
        int j = j0 + jj;
        int bm = j >> 3, h = j & 7;
        int b = bm / NBb, mB = bm % NBb;
        *(uint4*)&Qs[jj*PST + ch] =
            *(const uint4*)(g_q + (size_t)(b*Tt + mB*Cc + c)*DIMN + h*DHd + ch);
    }
    __syncthreads();

    float acc[13][4];
    #pragma unroll
    for (int nt = 0; nt < 13; nt++)
        #pragma unroll
        for (int i = 0; i < 4; i++) acc[nt][i] = 0.f;

    int arow = (wm*16 + g)*PST;
    #pragma unroll
    for (int k0 = 0; k0 < 64; k0 += 16) {
        unsigned A[4];
        A[0] = *(const unsigned*)&Qs[arow + k0 + 2*t];
        A[1] = *(const unsigned*)&Qs[arow + 8*PST + k0 + 2*t];
        A[2] = *(const unsigned*)&Qs[arow + k0 + 2*t + 8];
        A[3] = *(const unsigned*)&Qs[arow + 8*PST + k0 + 2*t + 8];
        #pragma unroll
        for (int nt = 0; nt < 13; nt++) {
            int n = wn*104 + nt*8 + g;
            unsigned B[2];
            B[0] = *(const unsigned*)&Rs[n*PST + k0 + 2*t];
            B[1] = *(const unsigned*)&Rs[n*PST + k0 + 2*t + 8];
            mma16(acc[nt], A, B);
        }
    }

    size_t jm0 = j0 + wm*16 + g, jm1 = jm0 + 8;
    #pragma unroll
    for (int nt = 0; nt < 13; nt++) {
        int col = wn*104 + nt*8 + 2*t;
        if (col < Cc - 1) {
            *(unsigned*)&g_pos[(jm0*Cc + c)*Cc + col] = h2u(acc[nt][0]*SCALE, acc[nt][1]*SCALE);
            *(unsigned*)&g_pos[(jm1*Cc + c)*Cc + col] = h2u(acc[nt][2]*SCALE, acc[nt][3]*SCALE);
        }
    }
}

// ---------------- fp16 attention v4: register-resident P, no-max softmax ----------------
// grid (2, NJ). 8 warps; warp w owns query rows [16w, 16w+16).
// halves: Ks[208][72] | Vst[64][216] | Qs[200][72] (V staging, then Q 128 rows)
#define AKST 72
#define AUST 216
#define KS_OFF  0
#define VST_OFF (208*AKST)
#define QS_OFF  (VST_OFF + 64*AUST)
#define ATTN_SMEM ((QS_OFF + 200*AKST)*2)   // 86,400 B

__global__ __launch_bounds__(256, 2)
void attn_mma() {
    extern __shared__ __half asm_[];
    __half* Ks  = asm_ + KS_OFF;
    __half* Vst = asm_ + VST_OFF;
    __half* Qs  = asm_ + QS_OFF;

    int tid = threadIdx.x, lane = tid & 31, warp = tid >> 5;
    int g = lane >> 2, t = lane & 3;
    int c0 = blockIdx.x * 128;
    int j  = blockIdx.y;
    int b = j / (NBb*Hh), mB = (j / Hh) % NBb, h = j & 7;
    int t0 = b*Tt + mB*Cc;
    const __half* kvb = g_kv + (size_t)t0*(2*DIMN) + h*DHd;

    // K rows (zero-pad r>=200); V rows staged into Qs region (stride 72)
    for (int i4 = tid; i4 < 208*8; i4 += 256) {
        int r = i4 >> 3, ch = (i4 & 7) * 8;
        uint4 v = make_uint4(0,0,0,0);
        if (r < Cc) v = *(const uint4*)(kvb + (size_t)r*(2*DIMN) + ch);
        *(uint4*)&Ks[r*AKST + ch] = v;
    }
    for (int i4 = tid; i4 < 200*8; i4 += 256) {
        int r = i4 >> 3, ch = (i4 & 7) * 8;
        *(uint4*)&Qs[r*AKST + ch] = *(const uint4*)(kvb + (size_t)r*(2*DIMN) + DIMN + ch);
    }
    __syncthreads();
    // transpose V -> Vst[d][r], zero r>=200
    for (int d = warp; d < 64; d += 8)
        for (int r = lane; r < 208; r += 32)
            Vst[d*AUST + r] = (r < Cc) ? Qs[r*AKST + d] : __float2half(0.f);
    __syncthreads();
    // Q rows (stride 72), zero rows c >= 200
    for (int i4 = tid; i4 < 128*8; i4 += 256) {
        int mr = i4 >> 3, ch = (i4 & 7) * 8;
        int c = c0 + mr;
        uint4 v = make_uint4(0,0,0,0);
        if (c < Cc) v = *(const uint4*)(g_q + (size_t)(t0 + c)*DIMN + h*DHd + ch);
        *(uint4*)&Qs[mr*AKST + ch] = v;
    }
    __syncthreads();

    if (c0 + (warp << 4) >= Cc) return;   // fully-invalid warps exit (no barriers left)

    int row = warp*16 + g;
    int cg0 = c0 + row, cg1 = cg0 + 8;
    const __half* p0 = g_pos + ((size_t)j*Cc + (cg0 < Cc ? cg0 : Cc-1))*Cc;
    const __half* p1 = g_pos + ((size_t)j*Cc + (cg1 < Cc ? cg1 : Cc-1))*Cc;

    // Q A-fragments: loaded once, reused by all 25 S tiles
    unsigned af[4][4];
    {
        int arow = row*AKST;
        #pragma unroll
        for (int ks = 0; ks < 4; ks++) {
            af[ks][0] = *(const unsigned*)&Qs[arow + ks*16 + 2*t];
            af[ks][1] = *(const unsigned*)&Qs[arow + 8*AKST + ks*16 + 2*t];
            af[ks][2] = *(const unsigned*)&Qs[arow + ks*16 + 2*t + 8];
            af[ks][3] = *(const unsigned*)&Qs[arow + 8*AKST + ks*16 + 2*t + 8];
        }
    }

    // ---- S tiles: MMA -> bias -> exp -> pack to half (register-resident P) ----
    unsigned ph[25][2];
    float s0 = 0.f, s1 = 0.f;
    #pragma unroll
    for (int nt = 0; nt < 25; nt++) {
        float sacc[4] = {0.f, 0.f, 0.f, 0.f};
        int n = nt*8 + g;
        #pragma unroll
        for (int ks = 0; ks < 4; ks++) {
            unsigned B[2];
            B[0] = *(const unsigned*)&Ks[n*AKST + ks*16 + 2*t];
            B[1] = *(const unsigned*)&Ks[n*AKST + ks*16 + 2*t + 8];
            mma16(sacc, af[ks], B);
        }
        int col = nt*8 + 2*t;
        float2 b0 = __half22float2(*(const __half2*)(p0 + col));
        float2 b1 = __half22float2(*(const __half2*)(p1 + col));
        float v0 = fmaf(sacc[0], SCALE, b0.x);
        float v1 = fmaf(sacc[1], SCALE, b0.y);
        float v2 = fmaf(sacc[2], SCALE, b1.x);
        float v3 = fmaf(sacc[3], SCALE, b1.y);
        float e0, e1, e2, e3;
        if (nt & 1) {
            e0 = exp2poly(v0 * LOG2E); e1 = exp2poly(v1 * LOG2E);
            e2 = exp2poly(v2 * LOG2E); e3 = exp2poly(v3 * LOG2E);
        } else {
            e0 = __expf(v0); e1 = __expf(v1);
            e2 = __expf(v2); e3 = __expf(v3);
        }
        s0 += e0 + e1;  s1 += e2 + e3;
        ph[nt][0] = h2u(e0, e1);
        ph[nt][1] = h2u(e2, e3);
    }
    #pragma unroll
    for (int o = 1; o <= 2; o <<= 1) {
        s0 += __shfl_xor_sync(~0u, s0, o);
        s1 += __shfl_xor_sync(~0u, s1, o);
    }
    float inv0 = 1.f / s0, inv1 = 1.f / s1;

    // ---- O = P V : P A-fragments straight from C-fragment registers ----
    float oacc[8][4];
    #pragma unroll
    for (int nt = 0; nt < 8; nt++)
        #pragma unroll
        for (int i = 0; i < 4; i++) oacc[nt][i] = 0.f;

    #pragma unroll
    for (int ks = 0; ks < 13; ks++) {
        unsigned A[4];
        A[0] = ph[2*ks][0];
        A[1] = ph[2*ks][1];
        if (2*ks + 1 < 25) { A[2] = ph[2*ks+1][0]; A[3] = ph[2*ks+1][1]; }
        else               { A[2] = 0u;            A[3] = 0u;            }
        int k0 = ks*16;
        #pragma unroll
        for (int nt = 0; nt < 8; nt++) {
            int n = nt*8 + g;
            unsigned B[2];
            B[0] = *(const unsigned*)&Vst[n*AUST + k0 + 2*t];
            B[1] = *(const unsigned*)&Vst[n*AUST + k0 + 2*t + 8];
            mma16(oacc[nt], A, B);
        }
    }

    __half* ob = g_att + (size_t)t0*DIMN + h*DHd;
    #pragma unroll
    for (int nt = 0; nt < 8; nt++) {
        int d0 = nt*8 + 2*t;
        if (cg0 < Cc)
            *(unsigned*)(ob + (size_t)cg0*DIMN + d0) = h2u(oacc[nt][0]*inv0, oacc[nt][1]*inv0);
        if (cg1 < Cc)
            *(unsigned*)(ob + (size_t)cg1*DIMN + d0) = h2u(oacc[nt][2]*inv1, oacc[nt][3]*inv1);
    }
}

// ---------------- launch ----------------
extern "C" void kernel_launch(void* const* d_in, const int* in_sizes, int n_in,
                              void* d_out, int out_size) {
    const float* x    = (const float*)d_in[0];
    const int*   dst  = (const int*)  d_in[1];
    const float* lng  = (const float*)d_in[2];
    const float* lnb  = (const float*)d_in[3];
    const float* Wq   = (const float*)d_in[4];
    const float* Wkv  = (const float*)d_in[5];
    const float* pe   = (const float*)d_in[6];
    const float* Wo   = (const float*)d_in[7];
    const float* bo   = (const float*)d_in[8];
    float* out = (float*)d_out;

    void* tmp;
    cudaGetSymbolAddress(&tmp, g_xn);   __half* xn  = (__half*)tmp;
    cudaGetSymbolAddress(&tmp, g_q);    __half* q   = (__half*)tmp;
    cudaGetSymbolAddress(&tmp, g_kv);   __half* kv  = (__half*)tmp;
    cudaGetSymbolAddress(&tmp, g_att);  __half* att = (__half*)tmp;
    cudaGetSymbolAddress(&tmp, g_wqT);  __half* wqT = (__half*)tmp;
    cudaGetSymbolAddress(&tmp, g_wkvT); __half* wkvT= (__half*)tmp;
    cudaGetSymbolAddress(&tmp, g_woT);  __half* woT = (__half*)tmp;

    cudaFuncSetAttribute(gemm_h<true>,  cudaFuncAttributeMaxDynamicSharedMemorySize, G_SMEM);
    cudaFuncSetAttribute(gemm_h<false>, cudaFuncAttributeMaxDynamicSharedMemorySize, G_SMEM);
    cudaFuncSetAttribute(pos_mma,  cudaFuncAttributeMaxDynamicSharedMemorySize, PM_SMEM);
    cudaFuncSetAttribute(attn_mma, cudaFuncAttributeMaxDynamicSharedMemorySize, ATTN_SMEM);

    // order keeps gemm_h<true> (q-proj) in the ncu-captured 4th slot
    ln_kernel<<<Mm, 128>>>(x, lng, lnb);
    transpose_h<<<dim3(16,16), 256>>>(Wq,  wqT,  DIMN, DIMN);
    transpose_h<<<dim3(16,32), 256>>>(Wkv, wkvT, DIMN, 2*DIMN);
    gemm_h<true><<<dim3(DIMN/BN,   Mm/BM), 256, G_SMEM>>>(xn, wqT,  nullptr, q,  DIMN);
    gemm_h<true><<<dim3(2*DIMN/BN, Mm/BM), 256, G_SMEM>>>(xn, wkvT, nullptr, kv, 2*DIMN);
    gather_kernel<<<(Cc*Cc*DHd + 255)/256, 256>>>(dst, pe);
    transpose_h<<<dim3(16,16), 256>>>(Wo, woT, DIMN, DIMN);
    pos_mma<<<dim3(NJ/64, Cc), 256, PM_SMEM>>>();
    attn_mma<<<dim3(2, NJ), 256, ATTN_SMEM>>>();
    gemm_h<false><<<dim3(DIMN/BN, Mm/BM), 256, G_SMEM>>>(att, woT, bo, out, DIMN);
}

// round 16
// speedup vs baseline: 1.1240x; 1.1240x over previous
#include <cuda_runtime.h>
#include <cuda_fp16.h>
#include <math.h>

// ---------------- problem constants ----------------
#define Bb   4
#define Tt   8000
#define DIMN 512
#define Hh   8
#define DHd  64
#define Cc   200
#define NBb  40
#define Mm   (Bb*Tt)        // 32000
#define NJ   (Bb*NBb*Hh)    // 1280
#define SCALE 0.125f
#define LOG2E 1.4426950408889634f

// ---------------- scratch (device globals; no allocation allowed) ----------------
__device__ __half g_xn [Mm*DIMN];
__device__ __half g_q  [Mm*DIMN];
__device__ __half g_kv [Mm*2*DIMN];
__device__ __half g_rel[Cc*Cc*DHd];
__device__ __half g_pos[(size_t)NJ*Cc*Cc];   // [j][c][r], scaled
__device__ __half g_att[Mm*DIMN];
__device__ __half g_wqT [DIMN*DIMN];         // [N][K]
__device__ __half g_wkvT[2*DIMN*DIMN];       // [N][K]
__device__ __half g_woT [DIMN*DIMN];         // [N][K]

__device__ __forceinline__ float exp2poly(float y) {
    y = fmaxf(y, -126.f);
    float tt = y + 12582912.f;
    float r  = y - (tt - 12582912.f);
    int   ni = __float_as_int(tt) - 0x4B400000;
    float p = 1.33336e-3f;
    p = fmaf(p, r, 9.61812e-3f);
    p = fmaf(p, r, 5.55041e-2f);
    p = fmaf(p, r, 2.402265e-1f);
    p = fmaf(p, r, 6.931472e-1f);
    p = fmaf(p, r, 1.f);
    return p * __int_as_float((ni + 127) << 23);
}

__device__ __forceinline__ unsigned h2u(float a, float b) {
    __half2 h = __floats2half2_rn(a, b);
    return *(unsigned*)&h;
}

// ---------------- weight transpose+convert: dst[n][k] = (half)src[k][n] ----------------
__global__ void transpose_h(const float* __restrict__ src, __half* __restrict__ dst,
                            int K, int N) {
    __shared__ float tile[32][33];
    int k0 = blockIdx.x*32, n0 = blockIdx.y*32;
    int tx = threadIdx.x & 31, ty = threadIdx.x >> 5;
    #pragma unroll
    for (int i = 0; i < 4; i++)
        tile[ty*4+i][tx] = src[(size_t)(k0+ty*4+i)*N + n0 + tx];
    __syncthreads();
    #pragma unroll
    for (int i = 0; i < 4; i++)
        dst[(size_t)(n0+ty*4+i)*K + k0 + tx] = __float2half(tile[tx][ty*4+i]);
}

// ---------------- LayerNorm ----------------
__global__ void ln_kernel(const float* __restrict__ x,
                          const float* __restrict__ g,
                          const float* __restrict__ bta) {
    int row = blockIdx.x;
    int t = threadIdx.x;
    float4 v = ((const float4*)(x + (size_t)row*DIMN))[t];
    float s  = v.x + v.y + v.z + v.w;
    float ss = v.x*v.x + v.y*v.y + v.z*v.z + v.w*v.w;
    #pragma unroll
    for (int o = 16; o; o >>= 1) {
        s  += __shfl_xor_sync(~0u, s,  o);
        ss += __shfl_xor_sync(~0u, ss, o);
    }
    __shared__ float rs[4], rss[4];
    int w = t >> 5;
    if ((t & 31) == 0) { rs[w] = s; rss[w] = ss; }
    __syncthreads();
    s  = rs[0]  + rs[1]  + rs[2]  + rs[3];
    ss = rss[0] + rss[1] + rss[2] + rss[3];
    float mu  = s  * (1.0f/DIMN);
    float var = ss * (1.0f/DIMN) - mu*mu;
    float inv = rsqrtf(var + 1e-5f);
    float4 gg = ((const float4*)g)[t];
    float4 bb = ((const float4*)bta)[t];
    uint2 o;
    o.x = h2u((v.x-mu)*inv*gg.x + bb.x, (v.y-mu)*inv*gg.y + bb.y);
    o.y = h2u((v.z-mu)*inv*gg.z + bb.z, (v.w-mu)*inv*gg.w + bb.w);
    ((uint2*)(g_xn + (size_t)row*DIMN))[t] = o;
}

// ---------------- rel gather (half) ----------------
__global__ void gather_kernel(const int* __restrict__ dists,
                              const float* __restrict__ pe) {
    int idx = blockIdx.x*256 + threadIdx.x;
    if (idx < Cc*Cc*DHd) {
        int cr = idx >> 6, d = idx & 63;
        g_rel[idx] = __float2half(pe[dists[cr]*DHd + d]);
    }
}

// ---------------- fp16 mma helper ----------------
__device__ __forceinline__ void mma16(float* c, const unsigned* a, const unsigned* b) {
    asm volatile("mma.sync.aligned.m16n8k16.row.col.f32.f16.f16.f32 "
        "{%0,%1,%2,%3}, {%4,%5,%6,%7}, {%8,%9}, {%0,%1,%2,%3};"
        : "+f"(c[0]), "+f"(c[1]), "+f"(c[2]), "+f"(c[3])
        : "r"(a[0]), "r"(a[1]), "r"(a[2]), "r"(a[3]), "r"(b[0]), "r"(b[1]));
}

// ---------------- fp16 GEMM: BK=32, 4-stage cp.async, scalar fragment loads ----------------
#define BM 128
#define BN 128
#define HST 40                       // 32 data halves + 8 pad (80B rows)
#define H_ST (128*HST)
#define G_SMEM (4*2*H_ST*2)          // 81,920 B

__device__ __forceinline__ void g_copy_h(
    const __half* __restrict__ A, const __half* __restrict__ WT,
    __half* As_st, __half* Bs_st, int m0, int n0, int k0, int tid)
{
    int row = tid >> 1, cq = (tid & 1) * 16;
    const __half* ga = A + (size_t)(m0 + row)*DIMN + k0 + cq;
    unsigned da = (unsigned)__cvta_generic_to_shared(As_st + row*HST + cq);
    asm volatile("cp.async.cg.shared.global [%0], [%1], 16;" :: "r"(da), "l"(ga));
    asm volatile("cp.async.cg.shared.global [%0], [%1], 16;" :: "r"(da+16), "l"(ga+8));
    const __half* gb = WT + (size_t)(n0 + row)*DIMN + k0 + cq;
    unsigned db = (unsigned)__cvta_generic_to_shared(Bs_st + row*HST + cq);
    asm volatile("cp.async.cg.shared.global [%0], [%1], 16;" :: "r"(db), "l"(gb));
    asm volatile("cp.async.cg.shared.global [%0], [%1], 16;" :: "r"(db+16), "l"(gb+8));
}

template<bool HOUT>
__global__ __launch_bounds__(256, 2)
void gemm_h(const __half* __restrict__ A, const __half* __restrict__ WT,
            const float* __restrict__ bias, void* __restrict__ outp, int N) {
    extern __shared__ __half hsm[];
    int tid  = threadIdx.x;
    int lane = tid & 31, warp = tid >> 5;
    int wm = warp >> 2, wn = warp & 3;
    int g = lane >> 2, t = lane & 3;
    int m0 = blockIdx.y*BM, n0 = blockIdx.x*BN;

    float acc[4][4][4];
    #pragma unroll
    for (int i=0;i<4;i++)
        #pragma unroll
        for (int jx=0;jx<4;jx++)
            #pragma unroll
            for (int r=0;r<4;r++) acc[i][jx][r]=0.f;

    const int NIT = DIMN / 32;   // 16
    #pragma unroll
    for (int s = 0; s < 3; s++) {
        g_copy_h(A, WT, hsm + s*2*H_ST, hsm + s*2*H_ST + H_ST, m0, n0, s*32, tid);
        asm volatile("cp.async.commit_group;");
    }

    for (int it = 0; it < NIT; it++) {
        asm volatile("cp.async.wait_group 2;");
        __syncthreads();
        int buf = it & 3;
        const __half* Apt = hsm + buf*2*H_ST;
        const __half* Bpt = Apt + H_ST;
        #pragma unroll
        for (int ks = 0; ks < 2; ks++) {
            int kk = ks*16;
            unsigned af[4][4], bf[4][2];
            #pragma unroll
            for (int mt = 0; mt < 4; mt++) {
                int mb = wm*64 + mt*16 + g;
                af[mt][0] = *(const unsigned*)&Apt[ mb   *HST + kk + 2*t];
                af[mt][1] = *(const unsigned*)&Apt[(mb+8)*HST + kk + 2*t];
                af[mt][2] = *(const unsigned*)&Apt[ mb   *HST + kk + 2*t + 8];
                af[mt][3] = *(const unsigned*)&Apt[(mb+8)*HST + kk + 2*t + 8];
            }
            #pragma unroll
            for (int nt = 0; nt < 4; nt++) {
                int nb = wn*32 + nt*8 + g;
                bf[nt][0] = *(const unsigned*)&Bpt[nb*HST + kk + 2*t];
                bf[nt][1] = *(const unsigned*)&Bpt[nb*HST + kk + 2*t + 8];
            }
            #pragma unroll
            for (int mt = 0; mt < 4; mt++)
                #pragma unroll
                for (int nt = 0; nt < 4; nt++)
                    mma16(acc[mt][nt], af[mt], bf[nt]);
        }
        int nxt = it + 3;
        if (nxt < NIT) {
            int sb = nxt & 3;
            g_copy_h(A, WT, hsm + sb*2*H_ST, hsm + sb*2*H_ST + H_ST, m0, n0, nxt*32, tid);
        }
        asm volatile("cp.async.commit_group;");
    }

    #pragma unroll
    for (int mt = 0; mt < 4; mt++) {
        int row = m0 + wm*64 + mt*16 + g;
        #pragma unroll
        for (int nt = 0; nt < 4; nt++) {
            int col = n0 + wn*32 + nt*8 + 2*t;
            if (HOUT) {
                __half* out = (__half*)outp;
                *(unsigned*)(out + (size_t)row*N + col)     = h2u(acc[mt][nt][0], acc[mt][nt][1]);
                *(unsigned*)(out + (size_t)(row+8)*N + col) = h2u(acc[mt][nt][2], acc[mt][nt][3]);
            } else {
                float* out = (float*)outp;
                float bv0 = bias ? bias[col]   : 0.f;
                float bv1 = bias ? bias[col+1] : 0.f;
                *(float2*)(out + (size_t)row*N + col) =
                    make_float2(acc[mt][nt][0]+bv0, acc[mt][nt][1]+bv1);
                *(float2*)(out + (size_t)(row+8)*N + col) =
                    make_float2(acc[mt][nt][2]+bv0, acc[mt][nt][3]+bv1);
            }
        }
    }
}

// ---------------- pos bias via fp16 MMA (round-8 version) ----------------
#define PST 72
#define PM_SMEM ((64*PST + 208*PST)*2)
__global__ __launch_bounds__(256)
void pos_mma() {
    extern __shared__ __half psm[];
    __half* Qs = psm;
    __half* Rs = psm + 64*PST;
    int tid = threadIdx.x, lane = tid & 31, warp = tid >> 5;
    int wm = warp >> 1, wn = warp & 1;
    int g = lane >> 2, t = lane & 3;
    int c  = blockIdx.y;
    int j0 = blockIdx.x * 64;

    for (int i4 = tid; i4 < 208*8; i4 += 256) {
        int r = i4 >> 3, ch = (i4 & 7) * 8;
        uint4 v = make_uint4(0,0,0,0);
        if (r < Cc) v = *(const uint4*)(g_rel + ((size_t)c*Cc + r)*DHd + ch);
        *(uint4*)&Rs[r*PST + ch] = v;
    }
    for (int i4 = tid; i4 < 64*8; i4 += 256) {
        int jj = i4 >> 3, ch = (i4 & 7) * 8;
        int j = j0 + jj;
        int bm = j >> 3, h = j & 7;
        int b = bm / NBb, mB = bm % NBb;
        *(uint4*)&Qs[jj*PST + ch] =
            *(const uint4*)(g_q + (size_t)(b*Tt + mB*Cc + c)*DIMN + h*DHd + ch);
    }
    __syncthreads();

    float acc[13][4];
    #pragma unroll
    for (int nt = 0; nt < 13; nt++)
        #pragma unroll
        for (int i = 0; i < 4; i++) acc[nt][i] = 0.f;

    int arow = (wm*16 + g)*PST;
    #pragma unroll
    for (int k0 = 0; k0 < 64; k0 += 16) {
        unsigned A[4];
        A[0] = *(const unsigned*)&Qs[arow + k0 + 2*t];
        A[1] = *(const unsigned*)&Qs[arow + 8*PST + k0 + 2*t];
        A[2] = *(const unsigned*)&Qs[arow + k0 + 2*t + 8];
        A[3] = *(const unsigned*)&Qs[arow + 8*PST + k0 + 2*t + 8];
        #pragma unroll
        for (int nt = 0; nt < 13; nt++) {
            int n = wn*104 + nt*8 + g;
            unsigned B[2];
            B[0] = *(const unsigned*)&Rs[n*PST + k0 + 2*t];
            B[1] = *(const unsigned*)&Rs[n*PST + k0 + 2*t + 8];
            mma16(acc[nt], A, B);
        }
    }

    size_t jm0 = j0 + wm*16 + g, jm1 = jm0 + 8;
    #pragma unroll
    for (int nt = 0; nt < 13; nt++) {
        int col = wn*104 + nt*8 + 2*t;
        if (col < Cc - 1) {
            *(unsigned*)&g_pos[(jm0*Cc + c)*Cc + col] = h2u(acc[nt][0]*SCALE, acc[nt][1]*SCALE);
            *(unsigned*)&g_pos[(jm1*Cc + c)*Cc + col] = h2u(acc[nt][2]*SCALE, acc[nt][3]*SCALE);
        }
    }
}

// ---------------- fp16 attention (round-11 version: 2 blocks/SM hint) ----------------
#define AKST 72
#define AUST 216
#define KS_OFF  0
#define VST_OFF (208*AKST)
#define U_OFF   (VST_OFF + 64*AUST)
#define ATTN_SMEM ((U_OFF + 128*AUST)*2)

__global__ __launch_bounds__(256, 2)
void attn_mma() {
    extern __shared__ __half asm_[];
    __half* Ks  = asm_ + KS_OFF;
    __half* Vst = asm_ + VST_OFF;
    __half* U   = asm_ + U_OFF;

    int tid = threadIdx.x, lane = tid & 31, warp = tid >> 5;
    int g = lane >> 2, t = lane & 3;
    int c0 = blockIdx.x * 128;
    int j  = blockIdx.y;
    int b = j / (NBb*Hh), mB = (j / Hh) % NBb, h = j & 7;
    int t0 = b*Tt + mB*Cc;
    const __half* kvb = g_kv + (size_t)t0*(2*DIMN) + h*DHd;

    // K rows: 208 x 64 halves (zero-pad r>=200)
    for (int i4 = tid; i4 < 208*8; i4 += 256) {
        int r = i4 >> 3, ch = (i4 & 7) * 8;
        uint4 v = make_uint4(0,0,0,0);
        if (r < Cc) v = *(const uint4*)(kvb + (size_t)r*(2*DIMN) + ch);
        *(uint4*)&Ks[r*AKST + ch] = v;
    }
    // V rows staged into U (stride 72)
    for (int i4 = tid; i4 < 200*8; i4 += 256) {
        int r = i4 >> 3, ch = (i4 & 7) * 8;
        *(uint4*)&U[r*AKST + ch] = *(const uint4*)(kvb + (size_t)r*(2*DIMN) + DIMN + ch);
    }
    __syncthreads();
    // transpose V -> Vst[d][r], zero r>=200
    for (int d = warp; d < 64; d += 8)
        for (int r = lane; r < 208; r += 32)
            Vst[d*AUST + r] = (r < Cc) ? U[r*AKST + d] : __float2half(0.f);
    __syncthreads();
    // Q rows (stride 216), zero rows c >= 200
    for (int i4 = tid; i4 < 128*8; i4 += 256) {
        int mr = i4 >> 3, ch = (i4 & 7) * 8;
        int c = c0 + mr;
        uint4 v = make_uint4(0,0,0,0);
        if (c < Cc) v = *(const uint4*)(g_q + (size_t)(t0 + c)*DIMN + h*DHd + ch);
        *(uint4*)&U[mr*AUST + ch] = v;
    }
    __syncthreads();

    if (c0 + (warp << 4) >= Cc) return;   // fully-invalid warps exit (no barriers left)

    int row = warp*16 + g;

    // ---- S = Q K^T : 25 n8-tiles, k=64 (4 k16 steps) ----
    float sacc[25][4];
    #pragma unroll
    for (int nt = 0; nt < 25; nt++)
        #pragma unroll
        for (int i = 0; i < 4; i++) sacc[nt][i] = 0.f;

    #pragma unroll
    for (int k0 = 0; k0 < 64; k0 += 16) {
        unsigned A[4];
        A[0] = *(const unsigned*)&U[row*AUST + k0 + 2*t];
        A[1] = *(const unsigned*)&U[(row+8)*AUST + k0 + 2*t];
        A[2] = *(const unsigned*)&U[row*AUST + k0 + 2*t + 8];
        A[3] = *(const unsigned*)&U[(row+8)*AUST + k0 + 2*t + 8];
        #pragma unroll
        for (int nt = 0; nt < 25; nt++) {
            int n = nt*8 + g;
            unsigned B[2];
            B[0] = *(const unsigned*)&Ks[n*AKST + k0 + 2*t];
            B[1] = *(const unsigned*)&Ks[n*AKST + k0 + 2*t + 8];
            mma16(sacc[nt], A, B);
        }
    }

    // ---- pos bias + warp-local softmax ----
    int cg0 = c0 + row, cg1 = cg0 + 8;
    const __half* p0 = g_pos + ((size_t)j*Cc + (cg0 < Cc ? cg0 : Cc-1))*Cc;
    const __half* p1 = g_pos + ((size_t)j*Cc + (cg1 < Cc ? cg1 : Cc-1))*Cc;
    float mx0 = -1e30f, mx1 = -1e30f;
    #pragma unroll
    for (int nt = 0; nt < 25; nt++) {
        int col = nt*8 + 2*t;
        float2 b0 = __half22float2(*(const __half2*)(p0 + col));
        float2 b1 = __half22float2(*(const __half2*)(p1 + col));
        sacc[nt][0] = fmaf(sacc[nt][0], SCALE, b0.x);
        sacc[nt][1] = fmaf(sacc[nt][1], SCALE, b0.y);
        sacc[nt][2] = fmaf(sacc[nt][2], SCALE, b1.x);
        sacc[nt][3] = fmaf(sacc[nt][3], SCALE, b1.y);
        mx0 = fmaxf(mx0, fmaxf(sacc[nt][0], sacc[nt][1]));
        mx1 = fmaxf(mx1, fmaxf(sacc[nt][2], sacc[nt][3]));
    }
    #pragma unroll
    for (int o = 1; o <= 2; o <<= 1) {
        mx0 = fmaxf(mx0, __shfl_xor_sync(~0u, mx0, o));
        mx1 = fmaxf(mx1, __shfl_xor_sync(~0u, mx1, o));
    }
    float nm0 = -mx0 * LOG2E, nm1 = -mx1 * LOG2E;
    float s0 = 0.f, s1 = 0.f;
    #pragma unroll
    for (int nt = 0; nt < 25; nt++) {
        if (nt & 1) {
            sacc[nt][0] = exp2poly(fmaf(sacc[nt][0], LOG2E, nm0));
            sacc[nt][1] = exp2poly(fmaf(sacc[nt][1], LOG2E, nm0));
            sacc[nt][2] = exp2poly(fmaf(sacc[nt][2], LOG2E, nm1));
            sacc[nt][3] = exp2poly(fmaf(sacc[nt][3], LOG2E, nm1));
        } else {
            sacc[nt][0] = __expf(sacc[nt][0] - mx0);
            sacc[nt][1] = __expf(sacc[nt][1] - mx0);
            sacc[nt][2] = __expf(sacc[nt][2] - mx1);
            sacc[nt][3] = __expf(sacc[nt][3] - mx1);
        }
        s0 += sacc[nt][0] + sacc[nt][1];
        s1 += sacc[nt][2] + sacc[nt][3];
    }
    #pragma unroll
    for (int o = 1; o <= 2; o <<= 1) {
        s0 += __shfl_xor_sync(~0u, s0, o);
        s1 += __shfl_xor_sync(~0u, s1, o);
    }
    float inv0 = 1.f / s0, inv1 = 1.f / s1;

    // store unnormalized P (half) over own Q rows; zero cols 200..207
    #pragma unroll
    for (int nt = 0; nt < 25; nt++) {
        int col = nt*8 + 2*t;
        *(unsigned*)&U[row*AUST + col]     = h2u(sacc[nt][0], sacc[nt][1]);
        *(unsigned*)&U[(row+8)*AUST + col] = h2u(sacc[nt][2], sacc[nt][3]);
    }
    {
        int col = 200 + 2*t;
        *(unsigned*)&U[row*AUST + col]     = 0u;
        *(unsigned*)&U[(row+8)*AUST + col] = 0u;
    }
    __syncwarp();

    // ---- O = P V : 8 n8 tiles, k = 208 (13 k16 steps) ----
    float oacc[8][4];
    #pragma unroll
    for (int nt = 0; nt < 8; nt++)
        #pragma unroll
        for (int i = 0; i < 4; i++) oacc[nt][i] = 0.f;

    #pragma unroll
    for (int k0 = 0; k0 < 208; k0 += 16) {
        unsigned A[4];
        A[0] = *(const unsigned*)&U[row*AUST + k0 + 2*t];
        A[1] = *(const unsigned*)&U[(row+8)*AUST + k0 + 2*t];
        A[2] = *(const unsigned*)&U[row*AUST + k0 + 2*t + 8];
        A[3] = *(const unsigned*)&U[(row+8)*AUST + k0 + 2*t + 8];
        #pragma unroll
        for (int nt = 0; nt < 8; nt++) {
            int n = nt*8 + g;
            unsigned B[2];
            B[0] = *(const unsigned*)&Vst[n*AUST + k0 + 2*t];
            B[1] = *(const unsigned*)&Vst[n*AUST + k0 + 2*t + 8];
            mma16(oacc[nt], A, B);
        }
    }

    __half* ob = g_att + (size_t)t0*DIMN + h*DHd;
    #pragma unroll
    for (int nt = 0; nt < 8; nt++) {
        int d0 = nt*8 + 2*t;
        if (cg0 < Cc)
            *(unsigned*)(ob + (size_t)cg0*DIMN + d0) = h2u(oacc[nt][0]*inv0, oacc[nt][1]*inv0);
        if (cg1 < Cc)
            *(unsigned*)(ob + (size_t)cg1*DIMN + d0) = h2u(oacc[nt][2]*inv1, oacc[nt][3]*inv1);
    }
}

// ---------------- launch ----------------
extern "C" void kernel_launch(void* const* d_in, const int* in_sizes, int n_in,
                              void* d_out, int out_size) {
    const float* x    = (const float*)d_in[0];
    const int*   dst  = (const int*)  d_in[1];
    const float* lng  = (const float*)d_in[2];
    const float* lnb  = (const float*)d_in[3];
    const float* Wq   = (const float*)d_in[4];
    const float* Wkv  = (const float*)d_in[5];
    const float* pe   = (const float*)d_in[6];
    const float* Wo   = (const float*)d_in[7];
    const float* bo   = (const float*)d_in[8];
    float* out = (float*)d_out;

    void* tmp;
    cudaGetSymbolAddress(&tmp, g_xn);   __half* xn  = (__half*)tmp;
    cudaGetSymbolAddress(&tmp, g_q);    __half* q   = (__half*)tmp;
    cudaGetSymbolAddress(&tmp, g_kv);   __half* kv  = (__half*)tmp;
    cudaGetSymbolAddress(&tmp, g_att);  __half* att = (__half*)tmp;
    cudaGetSymbolAddress(&tmp, g_wqT);  __half* wqT = (__half*)tmp;
    cudaGetSymbolAddress(&tmp, g_wkvT); __half* wkvT= (__half*)tmp;
    cudaGetSymbolAddress(&tmp, g_woT);  __half* woT = (__half*)tmp;

    cudaFuncSetAttribute(gemm_h<true>,  cudaFuncAttributeMaxDynamicSharedMemorySize, G_SMEM);
    cudaFuncSetAttribute(gemm_h<false>, cudaFuncAttributeMaxDynamicSharedMemorySize, G_SMEM);
    cudaFuncSetAttribute(pos_mma,  cudaFuncAttributeMaxDynamicSharedMemorySize, PM_SMEM);
    cudaFuncSetAttribute(attn_mma, cudaFuncAttributeMaxDynamicSharedMemorySize, ATTN_SMEM);

    // order keeps gemm_h<true> (q-proj) in the ncu-captured 4th slot
    ln_kernel<<<Mm, 128>>>(x, lng, lnb);
    transpose_h<<<dim3(16,16), 256>>>(Wq,  wqT,  DIMN, DIMN);
    transpose_h<<<dim3(16,32), 256>>>(Wkv, wkvT, DIMN, 2*DIMN);
    gemm_h<true><<<dim3(DIMN/BN,   Mm/BM), 256, G_SMEM>>>(xn, wqT,  nullptr, q,  DIMN);
    gemm_h<true><<<dim3(2*DIMN/BN, Mm/BM), 256, G_SMEM>>>(xn, wkvT, nullptr, kv, 2*DIMN);
    gather_kernel<<<(Cc*Cc*DHd + 255)/256, 256>>>(dst, pe);
    transpose_h<<<dim3(16,16), 256>>>(Wo, woT, DIMN, DIMN);
    pos_mma<<<dim3(NJ/64, Cc), 256, PM_SMEM>>>();
    attn_mma<<<dim3(2, NJ), 256, ATTN_SMEM>>>();
    gemm_h<false><<<dim3(DIMN/BN, Mm/BM), 256, G_SMEM>>>(att, woT, bo, out, DIMN);
}

// round 17
// speedup vs baseline: 1.1678x; 1.0390x over previous
#include <cuda_runtime.h>
#include <cuda_fp16.h>
#include <math.h>

// ---------------- problem constants ----------------
#define Bb   4
#define Tt   8000
#define DIMN 512
#define Hh   8
#define DHd  64
#define Cc   200
#define NBb  40
#define Mm   (Bb*Tt)        // 32000
#define NJ   (Bb*NBb*Hh)    // 1280
#define SCALE 0.125f
#define LOG2E 1.4426950408889634f

// ---------------- scratch (device globals; no allocation allowed) ----------------
__device__ __half g_xn [Mm*DIMN];
__device__ __half g_q  [Mm*DIMN];
__device__ __half g_kv [Mm*2*DIMN];
__device__ __half g_rel[Cc*Cc*DHd];
__device__ __half g_pos[(size_t)NJ*Cc*Cc];   // [j][c][r], scaled
__device__ __half g_att[Mm*DIMN];
__device__ __half g_wqT [DIMN*DIMN];         // [N][K]
__device__ __half g_wkvT[2*DIMN*DIMN];       // [N][K]
__device__ __half g_woT [DIMN*DIMN];         // [N][K]

__device__ __forceinline__ float exp2poly(float y) {
    y = fmaxf(y, -126.f);
    float tt = y + 12582912.f;
    float r  = y - (tt - 12582912.f);
    int   ni = __float_as_int(tt) - 0x4B400000;
    float p = 1.33336e-3f;
    p = fmaf(p, r, 9.61812e-3f);
    p = fmaf(p, r, 5.55041e-2f);
    p = fmaf(p, r, 2.402265e-1f);
    p = fmaf(p, r, 6.931472e-1f);
    p = fmaf(p, r, 1.f);
    return p * __int_as_float((ni + 127) << 23);
}

__device__ __forceinline__ unsigned h2u(float a, float b) {
    __half2 h = __floats2half2_rn(a, b);
    return *(unsigned*)&h;
}
__device__ __forceinline__ unsigned sptr(const void* p) {
    return (unsigned)__cvta_generic_to_shared(p);
}
__device__ __forceinline__ void ldm_x4(unsigned* r, unsigned a) {
    asm volatile("ldmatrix.sync.aligned.m8n8.x4.shared.b16 {%0,%1,%2,%3}, [%4];"
        : "=r"(r[0]), "=r"(r[1]), "=r"(r[2]), "=r"(r[3]) : "r"(a));
}

// ---------------- weight transpose+convert: dst[n][k] = (half)src[k][n] ----------------
__global__ void transpose_h(const float* __restrict__ src, __half* __restrict__ dst,
                            int K, int N) {
    __shared__ float tile[32][33];
    int k0 = blockIdx.x*32, n0 = blockIdx.y*32;
    int tx = threadIdx.x & 31, ty = threadIdx.x >> 5;
    #pragma unroll
    for (int i = 0; i < 4; i++)
        tile[ty*4+i][tx] = src[(size_t)(k0+ty*4+i)*N + n0 + tx];
    __syncthreads();
    #pragma unroll
    for (int i = 0; i < 4; i++)
        dst[(size_t)(n0+ty*4+i)*K + k0 + tx] = __float2half(tile[tx][ty*4+i]);
}

// ---------------- LayerNorm ----------------
__global__ void ln_kernel(const float* __restrict__ x,
                          const float* __restrict__ g,
                          const float* __restrict__ bta) {
    int row = blockIdx.x;
    int t = threadIdx.x;
    float4 v = ((const float4*)(x + (size_t)row*DIMN))[t];
    float s  = v.x + v.y + v.z + v.w;
    float ss = v.x*v.x + v.y*v.y + v.z*v.z + v.w*v.w;
    #pragma unroll
    for (int o = 16; o; o >>= 1) {
        s  += __shfl_xor_sync(~0u, s,  o);
        ss += __shfl_xor_sync(~0u, ss, o);
    }
    __shared__ float rs[4], rss[4];
    int w = t >> 5;
    if ((t & 31) == 0) { rs[w] = s; rss[w] = ss; }
    __syncthreads();
    s  = rs[0]  + rs[1]  + rs[2]  + rs[3];
    ss = rss[0] + rss[1] + rss[2] + rss[3];
    float mu  = s  * (1.0f/DIMN);
    float var = ss * (1.0f/DIMN) - mu*mu;
    float inv = rsqrtf(var + 1e-5f);
    float4 gg = ((const float4*)g)[t];
    float4 bb = ((const float4*)bta)[t];
    uint2 o;
    o.x = h2u((v.x-mu)*inv*gg.x + bb.x, (v.y-mu)*inv*gg.y + bb.y);
    o.y = h2u((v.z-mu)*inv*gg.z + bb.z, (v.w-mu)*inv*gg.w + bb.w);
    ((uint2*)(g_xn + (size_t)row*DIMN))[t] = o;
}

// ---------------- rel gather (half) ----------------
__global__ void gather_kernel(const int* __restrict__ dists,
                              const float* __restrict__ pe) {
    int idx = blockIdx.x*256 + threadIdx.x;
    if (idx < Cc*Cc*DHd) {
        int cr = idx >> 6, d = idx & 63;
        g_rel[idx] = __float2half(pe[dists[cr]*DHd + d]);
    }
}

// ---------------- fp16 mma helper ----------------
__device__ __forceinline__ void mma16(float* c, const unsigned* a, const unsigned* b) {
    asm volatile("mma.sync.aligned.m16n8k16.row.col.f32.f16.f16.f32 "
        "{%0,%1,%2,%3}, {%4,%5,%6,%7}, {%8,%9}, {%0,%1,%2,%3};"
        : "+f"(c[0]), "+f"(c[1]), "+f"(c[2]), "+f"(c[3])
        : "r"(a[0]), "r"(a[1]), "r"(a[2]), "r"(a[3]), "r"(b[0]), "r"(b[1]));
}

// ---------------- fp16 GEMM: BK=32, 4-stage cp.async, ldmatrix fragments (round-10) ----
#define BM 128
#define BN 128
#define HST 40                       // 32 data halves + 8 pad (80B rows)
#define H_ST (128*HST)
#define G_SMEM (4*2*H_ST*2)          // 81,920 B

__device__ __forceinline__ void g_copy_h(
    const __half* __restrict__ A, const __half* __restrict__ WT,
    __half* As_st, __half* Bs_st, int m0, int n0, int k0, int tid)
{
    int row = tid >> 1, cq = (tid & 1) * 16;
    const __half* ga = A + (size_t)(m0 + row)*DIMN + k0 + cq;
    unsigned da = sptr(As_st + row*HST + cq);
    asm volatile("cp.async.cg.shared.global [%0], [%1], 16;" :: "r"(da), "l"(ga));
    asm volatile("cp.async.cg.shared.global [%0], [%1], 16;" :: "r"(da+16), "l"(ga+8));
    const __half* gb = WT + (size_t)(n0 + row)*DIMN + k0 + cq;
    unsigned db = sptr(Bs_st + row*HST + cq);
    asm volatile("cp.async.cg.shared.global [%0], [%1], 16;" :: "r"(db), "l"(gb));
    asm volatile("cp.async.cg.shared.global [%0], [%1], 16;" :: "r"(db+16), "l"(gb+8));
}

template<bool HOUT>
__global__ __launch_bounds__(256, 2)
void gemm_h(const __half* __restrict__ A, const __half* __restrict__ WT,
            const float* __restrict__ bias, void* __restrict__ outp, int N) {
    extern __shared__ __half hsm[];
    int tid  = threadIdx.x;
    int lane = tid & 31, warp = tid >> 5;
    int wm = warp >> 2, wn = warp & 3;
    int g = lane >> 2, t = lane & 3;
    int m0 = blockIdx.y*BM, n0 = blockIdx.x*BN;

    // ldmatrix lane-address components
    int aR = lane & 15, aK = (lane >> 4) * 8;   // A x4: 16 rows x 16 k
    int bR = lane & 7,  bK = (lane >> 3) * 8;   // B x4: 8 rows x 32 k

    float acc[4][4][4];
    #pragma unroll
    for (int i=0;i<4;i++)
        #pragma unroll
        for (int jx=0;jx<4;jx++)
            #pragma unroll
            for (int r=0;r<4;r++) acc[i][jx][r]=0.f;

    const int NIT = DIMN / 32;   // 16
    #pragma unroll
    for (int s = 0; s < 3; s++) {
        g_copy_h(A, WT, hsm + s*2*H_ST, hsm + s*2*H_ST + H_ST, m0, n0, s*32, tid);
        asm volatile("cp.async.commit_group;");
    }

    for (int it = 0; it < NIT; it++) {
        asm volatile("cp.async.wait_group 2;");
        __syncthreads();
        int buf = it & 3;
        const __half* Apt = hsm + buf*2*H_ST;
        const __half* Bpt = Apt + H_ST;
        unsigned af[2][4][4], bf[4][4];
        #pragma unroll
        for (int mt = 0; mt < 4; mt++) {
            int rbase = (wm*64 + mt*16 + aR)*HST;
            ldm_x4(af[0][mt], sptr(&Apt[rbase + aK]));
            ldm_x4(af[1][mt], sptr(&Apt[rbase + 16 + aK]));
        }
        #pragma unroll
        for (int nt = 0; nt < 4; nt++)
            ldm_x4(bf[nt], sptr(&Bpt[(wn*32 + nt*8 + bR)*HST + bK]));
        #pragma unroll
        for (int ks = 0; ks < 2; ks++)
            #pragma unroll
            for (int mt = 0; mt < 4; mt++)
                #pragma unroll
                for (int nt = 0; nt < 4; nt++)
                    mma16(acc[mt][nt], af[ks][mt], &bf[nt][ks*2]);
        int nxt = it + 3;
        if (nxt < NIT) {
            int sb = nxt & 3;
            g_copy_h(A, WT, hsm + sb*2*H_ST, hsm + sb*2*H_ST + H_ST, m0, n0, nxt*32, tid);
        }
        asm volatile("cp.async.commit_group;");
    }

    #pragma unroll
    for (int mt = 0; mt < 4; mt++) {
        int row = m0 + wm*64 + mt*16 + g;
        #pragma unroll
        for (int nt = 0; nt < 4; nt++) {
            int col = n0 + wn*32 + nt*8 + 2*t;
            if (HOUT) {
                __half* out = (__half*)outp;
                *(unsigned*)(out + (size_t)row*N + col)     = h2u(acc[mt][nt][0], acc[mt][nt][1]);
                *(unsigned*)(out + (size_t)(row+8)*N + col) = h2u(acc[mt][nt][2], acc[mt][nt][3]);
            } else {
                float* out = (float*)outp;
                float bv0 = bias ? bias[col]   : 0.f;
                float bv1 = bias ? bias[col+1] : 0.f;
                *(float2*)(out + (size_t)row*N + col) =
                    make_float2(acc[mt][nt][0]+bv0, acc[mt][nt][1]+bv1);
                *(float2*)(out + (size_t)(row+8)*N + col) =
                    make_float2(acc[mt][nt][2]+bv0, acc[mt][nt][3]+bv1);
            }
        }
    }
}

// ---------------- pos bias via fp16 MMA (round-8 version, scalar loads) ----------------
#define PST 72
#define PM_SMEM ((64*PST + 208*PST)*2)
__global__ __launch_bounds__(256)
void pos_mma() {
    extern __shared__ __half psm[];
    __half* Qs = psm;
    __half* Rs = psm + 64*PST;
    int tid = threadIdx.x, lane = tid & 31, warp = tid >> 5;
    int wm = warp >> 1, wn = warp & 1;
    int g = lane >> 2, t = lane & 3;
    int c  = blockIdx.y;
    int j0 = blockIdx.x * 64;

    for (int i4 = tid; i4 < 208*8; i4 += 256) {
        int r = i4 >> 3, ch = (i4 & 7) * 8;
        uint4 v = make_uint4(0,0,0,0);
        if (r < Cc) v = *(const uint4*)(g_rel + ((size_t)c*Cc + r)*DHd + ch);
        *(uint4*)&Rs[r*PST + ch] = v;
    }
    for (int i4 = tid; i4 < 64*8; i4 += 256) {
        int jj = i4 >> 3, ch = (i4 & 7) * 8;
        int j = j0 + jj;
        int bm = j >> 3, h = j & 7;
        int b = bm / NBb, mB = bm % NBb;
        *(uint4*)&Qs[jj*PST + ch] =
            *(const uint4*)(g_q + (size_t)(b*Tt + mB*Cc + c)*DIMN + h*DHd + ch);
    }
    __syncthreads();

    float acc[13][4];
    #pragma unroll
    for (int nt = 0; nt < 13; nt++)
        #pragma unroll
        for (int i = 0; i < 4; i++) acc[nt][i] = 0.f;

    int arow = (wm*16 + g)*PST;
    #pragma unroll
    for (int k0 = 0; k0 < 64; k0 += 16) {
        unsigned A[4];
        A[0] = *(const unsigned*)&Qs[arow + k0 + 2*t];
        A[1] = *(const unsigned*)&Qs[arow + 8*PST + k0 + 2*t];
        A[2] = *(const unsigned*)&Qs[arow + k0 + 2*t + 8];
        A[3] = *(const unsigned*)&Qs[arow + 8*PST + k0 + 2*t + 8];
        #pragma unroll
        for (int nt = 0; nt < 13; nt++) {
            int n = wn*104 + nt*8 + g;
            unsigned B[2];
            B[0] = *(const unsigned*)&Rs[n*PST + k0 + 2*t];
            B[1] = *(const unsigned*)&Rs[n*PST + k0 + 2*t + 8];
            mma16(acc[nt], A, B);
        }
    }

    size_t jm0 = j0 + wm*16 + g, jm1 = jm0 + 8;
    #pragma unroll
    for (int nt = 0; nt < 13; nt++) {
        int col = wn*104 + nt*8 + 2*t;
        if (col < Cc - 1) {
            *(unsigned*)&g_pos[(jm0*Cc + c)*Cc + col] = h2u(acc[nt][0]*SCALE, acc[nt][1]*SCALE);
            *(unsigned*)&g_pos[(jm1*Cc + c)*Cc + col] = h2u(acc[nt][2]*SCALE, acc[nt][3]*SCALE);
        }
    }
}

// ---------------- fp16 attention v5: chunked S, register-resident P, no-max softmax ----
// grid (2, NJ). 8 warps; warp w owns query rows [16w, 16w+16).
// halves: Ks[208][72] | Vst[64][216] | Qs[200][72] (V staging, then Q 128 rows)
#define AKST 72
#define AUST 216
#define KS_OFF  0
#define VST_OFF (208*AKST)
#define QS_OFF  (VST_OFF + 64*AUST)
#define ATTN_SMEM ((QS_OFF + 200*AKST)*2)   // 86,400 B

__global__ __launch_bounds__(256, 2)
void attn_mma() {
    extern __shared__ __half asm_[];
    __half* Ks  = asm_ + KS_OFF;
    __half* Vst = asm_ + VST_OFF;
    __half* Qs  = asm_ + QS_OFF;

    int tid = threadIdx.x, lane = tid & 31, warp = tid >> 5;
    int g = lane >> 2, t = lane & 3;
    int c0 = blockIdx.x * 128;
    int j  = blockIdx.y;
    int b = j / (NBb*Hh), mB = (j / Hh) % NBb, h = j & 7;
    int t0 = b*Tt + mB*Cc;
    const __half* kvb = g_kv + (size_t)t0*(2*DIMN) + h*DHd;

    for (int i4 = tid; i4 < 208*8; i4 += 256) {
        int r = i4 >> 3, ch = (i4 & 7) * 8;
        uint4 v = make_uint4(0,0,0,0);
        if (r < Cc) v = *(const uint4*)(kvb + (size_t)r*(2*DIMN) + ch);
        *(uint4*)&Ks[r*AKST + ch] = v;
    }
    for (int i4 = tid; i4 < 200*8; i4 += 256) {
        int r = i4 >> 3, ch = (i4 & 7) * 8;
        *(uint4*)&Qs[r*AKST + ch] = *(const uint4*)(kvb + (size_t)r*(2*DIMN) + DIMN + ch);
    }
    __syncthreads();
    for (int d = warp; d < 64; d += 8)
        for (int r = lane; r < 208; r += 32)
            Vst[d*AUST + r] = (r < Cc) ? Qs[r*AKST + d] : __float2half(0.f);
    __syncthreads();
    for (int i4 = tid; i4 < 128*8; i4 += 256) {
        int mr = i4 >> 3, ch = (i4 & 7) * 8;
        int c = c0 + mr;
        uint4 v = make_uint4(0,0,0,0);
        if (c < Cc) v = *(const uint4*)(g_q + (size_t)(t0 + c)*DIMN + h*DHd + ch);
        *(uint4*)&Qs[mr*AKST + ch] = v;
    }
    __syncthreads();

    if (c0 + (warp << 4) >= Cc) return;   // fully-invalid warps exit (no barriers left)

    int row = warp*16 + g;
    int cg0 = c0 + row, cg1 = cg0 + 8;
    const __half* p0 = g_pos + ((size_t)j*Cc + (cg0 < Cc ? cg0 : Cc-1))*Cc;
    const __half* p1 = g_pos + ((size_t)j*Cc + (cg1 < Cc ? cg1 : Cc-1))*Cc;

    // Q A-fragments: loaded once, reused by all 25 S tiles
    unsigned af[4][4];
    {
        int arow = row*AKST;
        #pragma unroll
        for (int ks = 0; ks < 4; ks++) {
            af[ks][0] = *(const unsigned*)&Qs[arow + ks*16 + 2*t];
            af[ks][1] = *(const unsigned*)&Qs[arow + 8*AKST + ks*16 + 2*t];
            af[ks][2] = *(const unsigned*)&Qs[arow + ks*16 + 2*t + 8];
            af[ks][3] = *(const unsigned*)&Qs[arow + 8*AKST + ks*16 + 2*t + 8];
        }
    }

    // ---- S tiles in chunks of 5: batched MMA issue, then batched bias/exp/pack ----
    unsigned ph[25][2];
    float s0 = 0.f, s1 = 0.f;
    #pragma unroll
    for (int chk = 0; chk < 5; chk++) {
        float sacc[5][4];
        #pragma unroll
        for (int i = 0; i < 5; i++)
            #pragma unroll
            for (int r = 0; r < 4; r++) sacc[i][r] = 0.f;
        // 20 MMAs across 5 independent accumulator chains
        #pragma unroll
        for (int i = 0; i < 5; i++) {
            int n = (chk*5 + i)*8 + g;
            #pragma unroll
            for (int ks = 0; ks < 4; ks++) {
                unsigned B[2];
                B[0] = *(const unsigned*)&Ks[n*AKST + ks*16 + 2*t];
                B[1] = *(const unsigned*)&Ks[n*AKST + ks*16 + 2*t + 8];
                mma16(sacc[i], af[ks], B);
            }
        }
        // bias + exp + pack for this chunk
        #pragma unroll
        for (int i = 0; i < 5; i++) {
            int nt = chk*5 + i;
            int col = nt*8 + 2*t;
            float2 b0 = __half22float2(*(const __half2*)(p0 + col));
            float2 b1 = __half22float2(*(const __half2*)(p1 + col));
            float v0 = fmaf(sacc[i][0], SCALE, b0.x);
            float v1 = fmaf(sacc[i][1], SCALE, b0.y);
            float v2 = fmaf(sacc[i][2], SCALE, b1.x);
            float v3 = fmaf(sacc[i][3], SCALE, b1.y);
            float e0, e1, e2, e3;
            if (nt & 1) {
                e0 = exp2poly(v0 * LOG2E); e1 = exp2poly(v1 * LOG2E);
                e2 = exp2poly(v2 * LOG2E); e3 = exp2poly(v3 * LOG2E);
            } else {
                e0 = __expf(v0); e1 = __expf(v1);
                e2 = __expf(v2); e3 = __expf(v3);
            }
            s0 += e0 + e1;  s1 += e2 + e3;
            ph[nt][0] = h2u(e0, e1);
            ph[nt][1] = h2u(e2, e3);
        }
    }
    #pragma unroll
    for (int o = 1; o <= 2; o <<= 1) {
        s0 += __shfl_xor_sync(~0u, s0, o);
        s1 += __shfl_xor_sync(~0u, s1, o);
    }
    float inv0 = 1.f / s0, inv1 = 1.f / s1;

    // ---- O = P V : P A-fragments straight from C-fragment registers ----
    float oacc[8][4];
    #pragma unroll
    for (int nt = 0; nt < 8; nt++)
        #pragma unroll
        for (int i = 0; i < 4; i++) oacc[nt][i] = 0.f;

    #pragma unroll
    for (int ks = 0; ks < 13; ks++) {
        unsigned A[4];
        A[0] = ph[2*ks][0];
        A[1] = ph[2*ks][1];
        if (2*ks + 1 < 25) { A[2] = ph[2*ks+1][0]; A[3] = ph[2*ks+1][1]; }
        else               { A[2] = 0u;            A[3] = 0u;            }
        int k0 = ks*16;
        #pragma unroll
        for (int nt = 0; nt < 8; nt++) {
            int n = nt*8 + g;
            unsigned B[2];
            B[0] = *(const unsigned*)&Vst[n*AUST + k0 + 2*t];
            B[1] = *(const unsigned*)&Vst[n*AUST + k0 + 2*t + 8];
            mma16(oacc[nt], A, B);
        }
    }

    __half* ob = g_att + (size_t)t0*DIMN + h*DHd;
    #pragma unroll
    for (int nt = 0; nt < 8; nt++) {
        int d0 = nt*8 + 2*t;
        if (cg0 < Cc)
            *(unsigned*)(ob + (size_t)cg0*DIMN + d0) = h2u(oacc[nt][0]*inv0, oacc[nt][1]*inv0);
        if (cg1 < Cc)
            *(unsigned*)(ob + (size_t)cg1*DIMN + d0) = h2u(oacc[nt][2]*inv1, oacc[nt][3]*inv1);
    }
}

// ---------------- launch ----------------
extern "C" void kernel_launch(void* const* d_in, const int* in_sizes, int n_in,
                              void* d_out, int out_size) {
    const float* x    = (const float*)d_in[0];
    const int*   dst  = (const int*)  d_in[1];
    const float* lng  = (const float*)d_in[2];
    const float* lnb  = (const float*)d_in[3];
    const float* Wq   = (const float*)d_in[4];
    const float* Wkv  = (const float*)d_in[5];
    const float* pe   = (const float*)d_in[6];
    const float* Wo   = (const float*)d_in[7];
    const float* bo   = (const float*)d_in[8];
    float* out = (float*)d_out;

    void* tmp;
    cudaGetSymbolAddress(&tmp, g_xn);   __half* xn  = (__half*)tmp;
    cudaGetSymbolAddress(&tmp, g_q);    __half* q   = (__half*)tmp;
    cudaGetSymbolAddress(&tmp, g_kv);   __half* kv  = (__half*)tmp;
    cudaGetSymbolAddress(&tmp, g_att);  __half* att = (__half*)tmp;
    cudaGetSymbolAddress(&tmp, g_wqT);  __half* wqT = (__half*)tmp;
    cudaGetSymbolAddress(&tmp, g_wkvT); __half* wkvT= (__half*)tmp;
    cudaGetSymbolAddress(&tmp, g_woT);  __half* woT = (__half*)tmp;

    cudaFuncSetAttribute(gemm_h<true>,  cudaFuncAttributeMaxDynamicSharedMemorySize, G_SMEM);
    cudaFuncSetAttribute(gemm_h<false>, cudaFuncAttributeMaxDynamicSharedMemorySize, G_SMEM);
    cudaFuncSetAttribute(pos_mma,  cudaFuncAttributeMaxDynamicSharedMemorySize, PM_SMEM);
    cudaFuncSetAttribute(attn_mma, cudaFuncAttributeMaxDynamicSharedMemorySize, ATTN_SMEM);

    // order keeps gemm_h<true> (q-proj) in the ncu-captured 4th slot
    ln_kernel<<<Mm, 128>>>(x, lng, lnb);
    transpose_h<<<dim3(16,16), 256>>>(Wq,  wqT,  DIMN, DIMN);
    transpose_h<<<dim3(16,32), 256>>>(Wkv, wkvT, DIMN, 2*DIMN);
    gemm_h<true><<<dim3(DIMN/BN,   Mm/BM), 256, G_SMEM>>>(xn, wqT,  nullptr, q,  DIMN);
    gemm_h<true><<<dim3(2*DIMN/BN, Mm/BM), 256, G_SMEM>>>(xn, wkvT, nullptr, kv, 2*DIMN);
    gather_kernel<<<(Cc*Cc*DHd + 255)/256, 256>>>(dst, pe);
    transpose_h<<<dim3(16,16), 256>>>(Wo, woT, DIMN, DIMN);
    pos_mma<<<dim3(NJ/64, Cc), 256, PM_SMEM>>>();
    attn_mma<<<dim3(2, NJ), 256, ATTN_SMEM>>>();
    gemm_h<false><<<dim3(DIMN/BN, Mm/BM), 256, G_SMEM>>>(att, woT, bo, out, DIMN);
}